// round 6
// baseline (speedup 1.0000x reference)
#include <cuda_runtime.h>

#define BB 4
#define CC 12
#define HH0 512
#define NBC (BB*CC)          // 48
#define NSCALES 5
#define TS 32
#define TIN 42               // TS + 10
#define SPITCH 43
#define HPITCH 33
#define NTHR 256

__device__ float g_x0[(size_t)NBC*HH0*HH0];
__device__ float g_px1[(size_t)NBC*256*256];
__device__ float g_py1[(size_t)NBC*256*256];
__device__ float g_px2[(size_t)NBC*128*128];
__device__ float g_py2[(size_t)NBC*128*128];
__device__ float g_ss[NSCALES*NBC];
__device__ float g_cs[NSCALES*NBC];

// Device-side symbol resolution (host code must never touch these symbols).
__device__ __forceinline__ const float* src_x(int s) {
    return s == 0 ? g_x0 : (s == 1 ? g_px1 : g_px2);
}
__device__ __forceinline__ const float* src_y(int s) {
    return s == 1 ? g_py1 : g_py2;
}
__device__ __forceinline__ float* dst_x(int s) { return s == 0 ? g_px1 : g_px2; }
__device__ __forceinline__ float* dst_y(int s) { return s == 0 ? g_py1 : g_py2; }

// ---------------------------------------------------------------------------
__global__ __launch_bounds__(256) void softmax_x0(
    const float* __restrict__ pred, const int* __restrict__ tgt)
{
    if (blockIdx.x == 0 && threadIdx.x < NSCALES*NBC) {
        g_ss[threadIdx.x] = 0.f; g_cs[threadIdx.x] = 0.f;
    }
    const int HW = HH0*HH0;
    int p = blockIdx.x*blockDim.x + threadIdx.x;
    if (p >= BB*HW) return;
    int b  = p / HW;
    int hw = p - b*HW;
    const float* pp = pred + (size_t)b*CC*HW + hw;

    float v[CC];
    float mx = -1e30f;
#pragma unroll
    for (int c = 0; c < CC; c++) { v[c] = pp[(size_t)c*HW]; mx = fmaxf(mx, v[c]); }
    float s = 0.f;
#pragma unroll
    for (int c = 0; c < CC; c++) { v[c] = expf(v[c]-mx); s += v[c]; }
    float inv = 1.f/s;
    size_t base = (size_t)b*CC*HW + hw;
#pragma unroll
    for (int c = 0; c < CC; c++) g_x0[base + (size_t)c*HW] = v[c]*inv;
}

// ---------------------------------------------------------------------------
// Big-scale SSIM (scales 0 and 1) + fused 2x2 pooling.
// S0: y derived from tgt one-hot; conv(y^2) == conv(y) so the yy plane drops.
template<bool S0>
__global__ __launch_bounds__(NTHR) void ssim_kernel(
    const int* __restrict__ tgt, int Hs, int sidx)
{
    const int OH = Hs - 10;
    __shared__ float sx[TIN][SPITCH];
    __shared__ float sy[TIN][SPITCH];
    __shared__ float hb0[TIN][HPITCH];
    __shared__ float hb1[TIN][HPITCH];
    __shared__ float hb2[TIN][HPITCH];
    __shared__ float hb4[TIN][HPITCH];
    __shared__ float hb3s[S0 ? 1 : TIN][S0 ? 1 : HPITCH];
    __shared__ float rss[NTHR/32], rcs[NTHR/32];

    int bc  = blockIdx.z;
    int tid = threadIdx.x;
    int ty0 = blockIdx.y*TS, tx0 = blockIdx.x*TS;
    const float* xp = src_x(sidx) + (size_t)bc*Hs*Hs;
    const float* yp = S0 ? nullptr : (src_y(sidx) + (size_t)bc*Hs*Hs);
    const int*   tp = S0 ? (tgt + (size_t)(bc/CC)*Hs*Hs) : nullptr;
    int cls = bc % CC;

    constexpr float G[11] = {0.00102838f,0.00759870f,0.03600080f,0.10936070f,
                             0.21300560f,0.26601180f,0.21300560f,0.10936070f,
                             0.03600080f,0.00759870f,0.00102838f};

    // Load (TIN x TIN) tile, zero-fill outside.
    for (int i = tid; i < TIN*TIN; i += NTHR) {
        int r = i / TIN, c = i - r*TIN;
        int ih = ty0 + r, iw = tx0 + c;
        float xv = 0.f, yv = 0.f;
        if (ih < Hs && iw < Hs) {
            int o = ih*Hs + iw;
            xv = xp[o];
            yv = S0 ? ((tp[o] == cls) ? 1.f : 0.f) : yp[o];
        }
        sx[r][c] = xv; sy[r][c] = yv;
    }
    __syncthreads();

    // Fused 2x2 pooling of this tile's 32x32 region -> next scale input.
    {
        int Hd = Hs >> 1;
        float* xo = dst_x(sidx) + (size_t)bc*Hd*Hd;
        float* yo = dst_y(sidx) + (size_t)bc*Hd*Hd;
        int ph0 = blockIdx.y*16, pw0 = blockIdx.x*16;
        int pr = tid >> 4, pc = tid & 15;
        int r = pr*2, c = pc*2;
        float px = (sx[r][c]+sx[r][c+1]+sx[r+1][c]+sx[r+1][c+1])*0.25f;
        float py = (sy[r][c]+sy[r][c+1]+sy[r+1][c]+sy[r+1][c+1])*0.25f;
        int po = (ph0+pr)*Hd + (pw0+pc);
        xo[po] = px; yo[po] = py;
    }

    // Stage 1: horizontal blur, strips of 4 cols. 336 tasks.
    for (int task = tid; task < TIN*8; task += NTHR) {
        int r  = task >> 3;
        int c0 = (task & 7) << 2;
        float a0[4]={0,0,0,0}, a1[4]={0,0,0,0}, a2[4]={0,0,0,0};
        float a3[4]={0,0,0,0}, a4[4]={0,0,0,0};
#pragma unroll
        for (int i = 0; i < 14; i++) {
            float x = sx[r][c0+i], y = sy[r][c0+i];
            float xx = x*x, xy = x*y;
            float yy = S0 ? 0.f : y*y;
#pragma unroll
            for (int j = 0; j < 4; j++) {
                int k = i - j;
                if (k >= 0 && k < 11) {
                    a0[j] = fmaf(G[k], x,  a0[j]);
                    a1[j] = fmaf(G[k], y,  a1[j]);
                    a2[j] = fmaf(G[k], xx, a2[j]);
                    if (!S0) a3[j] = fmaf(G[k], yy, a3[j]);
                    a4[j] = fmaf(G[k], xy, a4[j]);
                }
            }
        }
#pragma unroll
        for (int j = 0; j < 4; j++) {
            hb0[r][c0+j] = a0[j]; hb1[r][c0+j] = a1[j];
            hb2[r][c0+j] = a2[j]; hb4[r][c0+j] = a4[j];
            if (!S0) hb3s[r][c0+j] = a3[j];
        }
    }
    __syncthreads();

    // Stage 2: vertical blur + SSIM, strips of 4 rows. 256 tasks.
    float lss = 0.f, lcs = 0.f;
    {
        int c  = tid & 31;
        int r0 = (tid >> 5) << 2;
        float m1[4]={0,0,0,0}, m2[4]={0,0,0,0}, e11[4]={0,0,0,0};
        float e22[4]={0,0,0,0}, e12[4]={0,0,0,0};
#pragma unroll
        for (int i = 0; i < 14; i++) {
            int row = r0 + i;
            float v0 = hb0[row][c], v1 = hb1[row][c];
            float v2 = hb2[row][c], v4 = hb4[row][c];
            float v3 = S0 ? 0.f : hb3s[row][c];
#pragma unroll
            for (int j = 0; j < 4; j++) {
                int k = i - j;
                if (k >= 0 && k < 11) {
                    m1[j]  = fmaf(G[k], v0, m1[j]);
                    m2[j]  = fmaf(G[k], v1, m2[j]);
                    e11[j] = fmaf(G[k], v2, e11[j]);
                    if (!S0) e22[j] = fmaf(G[k], v3, e22[j]);
                    e12[j] = fmaf(G[k], v4, e12[j]);
                }
            }
        }
        int ow = tx0 + c;
#pragma unroll
        for (int j = 0; j < 4; j++) {
            int oh = ty0 + r0 + j;
            if (oh < OH && ow < OH) {
                float M1 = m1[j], M2 = m2[j];
                float E22 = S0 ? M2 : e22[j];
                float m11 = M1*M1, m22 = M2*M2, m12 = M1*M2;
                float v1 = e11[j] - m11, v2 = E22 - m22, cov = e12[j] - m12;
                float cs = __fdividef(2.f*cov + 0.0009f, v1 + v2 + 0.0009f);
                float sv = __fdividef(2.f*m12 + 0.0001f, m11 + m22 + 0.0001f) * cs;
                lss += sv; lcs += cs;
            }
        }
    }

#pragma unroll
    for (int o = 16; o; o >>= 1) {
        lss += __shfl_down_sync(0xffffffffu, lss, o);
        lcs += __shfl_down_sync(0xffffffffu, lcs, o);
    }
    if ((tid & 31) == 0) { rss[tid>>5] = lss; rcs[tid>>5] = lcs; }
    __syncthreads();
    if (tid == 0) {
        float ts = 0.f, tc = 0.f;
#pragma unroll
        for (int w = 0; w < NTHR/32; w++) { ts += rss[w]; tc += rcs[w]; }
        atomicAdd(&g_ss[sidx*NBC + bc], ts);
        atomicAdd(&g_cs[sidx*NBC + bc], tc);
    }
}

// ---------------------------------------------------------------------------
// Small scales (2,3,4) fused: one block per bc, everything in dynamic smem.
#define P2 129
#define P3 65
#define P4 33
#define SZ2 (128*P2)
#define SZ3 (64*P3)
#define SZ4 (32*P4)
#define HBP (42*HPITCH)
#define DSM_FLOATS (2*SZ2 + 2*SZ3 + 2*SZ4 + 5*HBP)

__device__ __forceinline__ float sld(const float* a, int pitch, int Hs, int r, int c) {
    return (r < Hs && c < Hs) ? a[r*pitch + c] : 0.f;
}

__device__ void ssim_smem(const float* xs, const float* ys, int Hs, int pitch,
                          float* hb, int tid, float* red, int sidx, int bc)
{
    constexpr float G[11] = {0.00102838f,0.00759870f,0.03600080f,0.10936070f,
                             0.21300560f,0.26601180f,0.21300560f,0.10936070f,
                             0.03600080f,0.00759870f,0.00102838f};
    float* hb0 = hb;           float* hb1 = hb + HBP;
    float* hb2 = hb + 2*HBP;   float* hb3 = hb + 3*HBP;
    float* hb4 = hb + 4*HBP;
    const int OH = Hs - 10;
    const int nt = Hs >> 5;

    float lss = 0.f, lcs = 0.f;
    for (int tz = 0; tz < nt*nt; tz++) {
        int ty0 = (tz / nt)*TS, tx0 = (tz % nt)*TS;
        __syncthreads();  // hb reuse across tiles/scales

        for (int task = tid; task < TIN*8; task += NTHR) {
            int r  = task >> 3;
            int c0 = (task & 7) << 2;
            int ih = ty0 + r;
            float a0[4]={0,0,0,0}, a1[4]={0,0,0,0}, a2[4]={0,0,0,0};
            float a3[4]={0,0,0,0}, a4[4]={0,0,0,0};
#pragma unroll
            for (int i = 0; i < 14; i++) {
                int iw = tx0 + c0 + i;
                float x = sld(xs, pitch, Hs, ih, iw);
                float y = sld(ys, pitch, Hs, ih, iw);
                float xx = x*x, yy = y*y, xy = x*y;
#pragma unroll
                for (int j = 0; j < 4; j++) {
                    int k = i - j;
                    if (k >= 0 && k < 11) {
                        a0[j] = fmaf(G[k], x,  a0[j]);
                        a1[j] = fmaf(G[k], y,  a1[j]);
                        a2[j] = fmaf(G[k], xx, a2[j]);
                        a3[j] = fmaf(G[k], yy, a3[j]);
                        a4[j] = fmaf(G[k], xy, a4[j]);
                    }
                }
            }
#pragma unroll
            for (int j = 0; j < 4; j++) {
                int o = r*HPITCH + c0 + j;
                hb0[o]=a0[j]; hb1[o]=a1[j]; hb2[o]=a2[j]; hb3[o]=a3[j]; hb4[o]=a4[j];
            }
        }
        __syncthreads();

        {
            int c  = tid & 31;
            int r0 = (tid >> 5) << 2;
            float m1[4]={0,0,0,0}, m2[4]={0,0,0,0}, e11[4]={0,0,0,0};
            float e22[4]={0,0,0,0}, e12[4]={0,0,0,0};
#pragma unroll
            for (int i = 0; i < 14; i++) {
                int o = (r0+i)*HPITCH + c;
                float v0 = hb0[o], v1 = hb1[o], v2 = hb2[o], v3 = hb3[o], v4 = hb4[o];
#pragma unroll
                for (int j = 0; j < 4; j++) {
                    int k = i - j;
                    if (k >= 0 && k < 11) {
                        m1[j]  = fmaf(G[k], v0, m1[j]);
                        m2[j]  = fmaf(G[k], v1, m2[j]);
                        e11[j] = fmaf(G[k], v2, e11[j]);
                        e22[j] = fmaf(G[k], v3, e22[j]);
                        e12[j] = fmaf(G[k], v4, e12[j]);
                    }
                }
            }
            int ow = tx0 + c;
#pragma unroll
            for (int j = 0; j < 4; j++) {
                int oh = ty0 + r0 + j;
                if (oh < OH && ow < OH) {
                    float M1 = m1[j], M2 = m2[j];
                    float m11 = M1*M1, m22 = M2*M2, m12 = M1*M2;
                    float v1 = e11[j] - m11, v2 = e22[j] - m22, cov = e12[j] - m12;
                    float cs = __fdividef(2.f*cov + 0.0009f, v1 + v2 + 0.0009f);
                    float sv = __fdividef(2.f*m12 + 0.0001f, m11 + m22 + 0.0001f) * cs;
                    lss += sv; lcs += cs;
                }
            }
        }
    }

#pragma unroll
    for (int o = 16; o; o >>= 1) {
        lss += __shfl_down_sync(0xffffffffu, lss, o);
        lcs += __shfl_down_sync(0xffffffffu, lcs, o);
    }
    if ((tid & 31) == 0) { red[tid>>5] = lss; red[8 + (tid>>5)] = lcs; }
    __syncthreads();
    if (tid == 0) {
        float ts = 0.f, tc = 0.f;
#pragma unroll
        for (int w = 0; w < 8; w++) { ts += red[w]; tc += red[8+w]; }
        g_ss[sidx*NBC + bc] = ts;
        g_cs[sidx*NBC + bc] = tc;
    }
    __syncthreads();
}

__device__ void pool_smem(const float* s, float* d, int Hs, int sp, int dp, int tid)
{
    int Hd = Hs >> 1;
    for (int i = tid; i < Hd*Hd; i += NTHR) {
        int r = i / Hd, c = i - r*Hd;
        d[r*dp + c] = (s[(2*r)*sp + 2*c]   + s[(2*r)*sp + 2*c+1]
                     + s[(2*r+1)*sp + 2*c] + s[(2*r+1)*sp + 2*c+1])*0.25f;
    }
}

__global__ __launch_bounds__(NTHR, 1) void ssim_small()
{
    extern __shared__ float dsm[];
    __shared__ float red[16];
    float* x2 = dsm;
    float* y2 = x2 + SZ2;
    float* x3 = y2 + SZ2;
    float* y3 = x3 + SZ3;
    float* x4 = y3 + SZ3;
    float* y4 = x4 + SZ4;
    float* hb = y4 + SZ4;

    int bc  = blockIdx.x;
    int tid = threadIdx.x;
    const float* xg = g_px2 + (size_t)bc*128*128;
    const float* yg = g_py2 + (size_t)bc*128*128;

    for (int i = tid; i < 128*128; i += NTHR) {
        int r = i >> 7, c = i & 127;
        x2[r*P2 + c] = xg[i];
        y2[r*P2 + c] = yg[i];
    }
    __syncthreads();
    pool_smem(x2, x3, 128, P2, P3, tid);
    pool_smem(y2, y3, 128, P2, P3, tid);
    __syncthreads();
    pool_smem(x3, x4, 64, P3, P4, tid);
    pool_smem(y3, y4, 64, P3, P4, tid);
    __syncthreads();

    ssim_smem(x2, y2, 128, P2, hb, tid, red, 2, bc);
    ssim_smem(x3, y3, 64,  P3, hb, tid, red, 3, bc);
    ssim_smem(x4, y4, 32,  P4, hb, tid, red, 4, bc);
}

// ---------------------------------------------------------------------------
__global__ void finalize(float* __restrict__ out)
{
    __shared__ float sm[NBC];
    int t = threadIdx.x;
    const float Wt[5]  = {0.0448f, 0.2856f, 0.3001f, 0.2363f, 0.1333f};
    const float cnt[5] = {502.f*502.f, 246.f*246.f, 118.f*118.f, 54.f*54.f, 22.f*22.f};
    if (t < NBC) {
        float ms = 1.f;
#pragma unroll
        for (int s = 0; s < NSCALES; s++) {
            float acc = (s == NSCALES-1) ? g_ss[s*NBC + t] : g_cs[s*NBC + t];
            float v = fmaxf(acc / cnt[s], 0.f);
            ms *= powf(v, Wt[s]);
        }
        sm[t] = ms;
    }
    __syncthreads();
    if (t == 0) {
        float a = 0.f;
#pragma unroll
        for (int i = 0; i < NBC; i++) a += sm[i];
        out[0] = 1.f - a / (float)NBC;
    }
}

// ---------------------------------------------------------------------------
extern "C" void kernel_launch(void* const* d_in, const int* in_sizes, int n_in,
                              void* d_out, int out_size)
{
    const float* pred = (const float*)d_in[0];
    const int*   tgt  = (const int*)d_in[1];
    float*       out  = (float*)d_out;

    cudaFuncSetAttribute(ssim_small,
        cudaFuncAttributeMaxDynamicSharedMemorySize, DSM_FLOATS*4);

    int np = BB*HH0*HH0;
    softmax_x0<<<(np + 255)/256, 256>>>(pred, tgt);

    {
        dim3 grid(16, 16, NBC);
        ssim_kernel<true><<<grid, NTHR>>>(tgt, 512, 0);
    }
    {
        dim3 grid(8, 8, NBC);
        ssim_kernel<false><<<grid, NTHR>>>(tgt, 256, 1);
    }
    ssim_small<<<NBC, NTHR, DSM_FLOATS*4>>>();

    finalize<<<1, 64>>>(out);
}